// round 1
// baseline (speedup 1.0000x reference)
#include <cuda_runtime.h>
#include <cuda_bf16.h>

// Problem constants
#define BB 4
#define CC 192
#define O3 576          // 3*CC
#define HEADS 8
#define HD 24
#define IMG 256
#define NPIX 65536      // IMG*IMG

// ---------------- scratch (device globals; no cudaMalloc allowed) ----------------
__device__ float g_qkv [ (size_t)BB * O3 * NPIX ];   // post 1x1-conv GEMM
__device__ float g_qkvc[ (size_t)BB * O3 * NPIX ];   // post depthwise conv
__device__ float g_gram[ BB * HEADS * HD * HD ];     // Q.K^T per (b,h)
__device__ float g_ss  [ BB * 384 ];                 // sum of squares: [0,192)=q, [192,384)=k
__device__ float g_w2  [ BB * CC * CC ];             // folded attn*proj weights

// ---------------- f32x2 helpers (sm_100+ packed fp32 FMA) ----------------
__device__ __forceinline__ unsigned long long pk2(float x, float y) {
    unsigned long long r;
    asm("mov.b64 %0, {%1, %2};" : "=l"(r) : "f"(x), "f"(y));
    return r;
}
__device__ __forceinline__ float2 upk(unsigned long long v) {
    float2 f;
    asm("mov.b64 {%0, %1}, %2;" : "=f"(f.x), "=f"(f.y) : "l"(v));
    return f;
}
__device__ __forceinline__ void fma2(unsigned long long& c, unsigned long long a, unsigned long long b) {
    asm("fma.rn.f32x2 %0, %1, %2, %0;" : "+l"(c) : "l"(a), "l"(b));
}

// ---------------- K0: zero accumulators ----------------
__global__ void zero_kernel(float* __restrict__ gram, float* __restrict__ ss) {
    int i = blockIdx.x * 256 + threadIdx.x;
    if (i < BB * HEADS * HD * HD) gram[i] = 0.f;
    if (i < BB * 384) ss[i] = 0.f;
}

// ---------------- K1/K5: batched GEMM  C[b][m][n] = sum_k A[b][m][k] * B[b][k][n]
// K = 192 fixed, N row stride = 65536 fixed. Tile 64(M) x 128(N) x 16(K), 256 threads,
// per-thread 4x8 micro-tile computed with packed f32x2 FMA.
__global__ void __launch_bounds__(256) gemm_f32x2(
    const float* __restrict__ A, long aBatch,
    const float* __restrict__ Bm, long bBatch,
    float* __restrict__ Cm, long cBatch)
{
    const int b = blockIdx.z;
    const float* Ab = A + (long)b * aBatch;
    const float* Bb = Bm + (long)b * bBatch;
    float* Cb = Cm + (long)b * cBatch;
    const int n0 = blockIdx.x * 128;
    const int m0 = blockIdx.y * 64;

    __shared__ float As[16][64];
    __shared__ __align__(16) float Bs[16][128];

    const int tid = threadIdx.x;
    const int tm = tid >> 4;          // 0..15
    const int tn = tid & 15;          // 0..15

    unsigned long long acc[4][4];
#pragma unroll
    for (int i = 0; i < 4; i++)
#pragma unroll
        for (int j = 0; j < 4; j++) acc[i][j] = 0ull;

    const int arow = tid >> 2;          // 0..63
    const int acol4 = (tid & 3) * 4;    // 0,4,8,12
    const int brow = tid >> 5;          // 0..7
    const int bcol = (tid & 31) * 4;    // 0..124

    for (int k0 = 0; k0 < 192; k0 += 16) {
        float4 av = *(const float4*)(Ab + (long)(m0 + arow) * 192 + k0 + acol4);
        As[acol4 + 0][arow] = av.x;
        As[acol4 + 1][arow] = av.y;
        As[acol4 + 2][arow] = av.z;
        As[acol4 + 3][arow] = av.w;

        float4 bv0 = *(const float4*)(Bb + (long)(k0 + brow) * 65536 + n0 + bcol);
        float4 bv1 = *(const float4*)(Bb + (long)(k0 + brow + 8) * 65536 + n0 + bcol);
        *(float4*)&Bs[brow][bcol] = bv0;
        *(float4*)&Bs[brow + 8][bcol] = bv1;
        __syncthreads();

#pragma unroll
        for (int k = 0; k < 16; k++) {
            unsigned long long aa[4];
#pragma unroll
            for (int i = 0; i < 4; i++) {
                float a = As[k][tm * 4 + i];
                aa[i] = pk2(a, a);
            }
            const unsigned long long* B2 = (const unsigned long long*)&Bs[k][tn * 8];
            unsigned long long bb0 = B2[0], bb1 = B2[1], bb2 = B2[2], bb3 = B2[3];
#pragma unroll
            for (int i = 0; i < 4; i++) {
                fma2(acc[i][0], aa[i], bb0);
                fma2(acc[i][1], aa[i], bb1);
                fma2(acc[i][2], aa[i], bb2);
                fma2(acc[i][3], aa[i], bb3);
            }
        }
        __syncthreads();
    }

#pragma unroll
    for (int i = 0; i < 4; i++) {
        float2 u0 = upk(acc[i][0]), u1 = upk(acc[i][1]);
        float2 u2 = upk(acc[i][2]), u3 = upk(acc[i][3]);
        float4* dst = (float4*)(Cb + (long)(m0 + tm * 4 + i) * 65536 + n0 + tn * 8);
        dst[0] = make_float4(u0.x, u0.y, u1.x, u1.y);
        dst[1] = make_float4(u2.x, u2.y, u3.x, u3.y);
    }
}

// ---------------- K2: depthwise 3x3 conv (pad 1) + fused sum-of-squares for q,k channels
__global__ void __launch_bounds__(256) dwconv_kernel(
    const float* __restrict__ in, const float* __restrict__ w,
    float* __restrict__ out, float* __restrict__ ss)
{
    const int plane = blockIdx.x;        // b*576 + ch
    const int ch = plane % O3;
    const int y0 = blockIdx.y * 16;

    __shared__ float s[18][258];
    __shared__ float red[8];

    const float* ip = in + (long)plane * NPIX;
    const int tid = threadIdx.x;

    for (int i = tid; i < 18 * 258; i += 256) {
        int r = i / 258, c = i - r * 258;
        int gy = y0 - 1 + r, gx = c - 1;
        float v = 0.f;
        if (gy >= 0 && gy < IMG && (unsigned)gx < (unsigned)IMG) v = ip[gy * IMG + gx];
        s[r][c] = v;
    }
    const float* wp = w + ch * 9;
    float w00 = wp[0], w01 = wp[1], w02 = wp[2];
    float w10 = wp[3], w11 = wp[4], w12 = wp[5];
    float w20 = wp[6], w21 = wp[7], w22 = wp[8];
    __syncthreads();

    float* op = out + (long)plane * NPIX + (long)y0 * IMG;
    const int x = tid;
    float sq = 0.f;
#pragma unroll
    for (int yy = 0; yy < 16; yy++) {
        float v = s[yy    ][x] * w00 + s[yy    ][x + 1] * w01 + s[yy    ][x + 2] * w02
                + s[yy + 1][x] * w10 + s[yy + 1][x + 1] * w11 + s[yy + 1][x + 2] * w12
                + s[yy + 2][x] * w20 + s[yy + 2][x + 1] * w21 + s[yy + 2][x + 2] * w22;
        op[yy * IMG + x] = v;
        sq += v * v;
    }

    if (ch < 384) {  // q or k channel: accumulate sum of squares
#pragma unroll
        for (int o = 16; o > 0; o >>= 1) sq += __shfl_xor_sync(0xffffffffu, sq, o);
        if ((tid & 31) == 0) red[tid >> 5] = sq;
        __syncthreads();
        if (tid == 0) {
            float t = 0.f;
#pragma unroll
            for (int i = 0; i < 8; i++) t += red[i];
            atomicAdd(&ss[(plane / O3) * 384 + ch], t);
        }
    }
}

// ---------------- K3: Gram matrices  G[b][h][d][e] = sum_n qc[d][n]*kc[e][n]
__global__ void __launch_bounds__(576) gram_kernel(
    const float* __restrict__ qkvc, float* __restrict__ gram)
{
    const int b = blockIdx.z, h = blockIdx.y;
    const int nbase = blockIdx.x * 8192;

    __shared__ float sq[24][129];
    __shared__ float sk[24][129];

    const float* qp = qkvc + ((long)b * O3 + h * HD) * NPIX;
    const float* kp = qp + (long)CC * NPIX;

    const int tid = threadIdx.x;       // 576
    const int d = tid / 24, e = tid % 24;
    float acc = 0.f;

    for (int sc = 0; sc < 64; sc++) {
        const int n0 = nbase + sc * 128;
        for (int i = tid; i < 24 * 128; i += 576) {
            int r = i >> 7, c = i & 127;
            sq[r][c] = qp[(long)r * NPIX + n0 + c];
            sk[r][c] = kp[(long)r * NPIX + n0 + c];
        }
        __syncthreads();
#pragma unroll 8
        for (int p = 0; p < 128; p++) acc += sq[d][p] * sk[e][p];
        __syncthreads();
    }
    atomicAdd(&gram[(((long)b * HEADS + h) * HD + d) * HD + e], acc);
}

// ---------------- K4: normalize + softmax + fold projection into W2
__global__ void __launch_bounds__(192) attn_w2_kernel(
    const float* __restrict__ gram, const float* __restrict__ ss,
    const float* __restrict__ projw, const float* __restrict__ temp,
    float* __restrict__ w2)
{
    const int bh = blockIdx.x;
    const int b = bh >> 3, h = bh & 7;
    __shared__ float attn[24][24];
    __shared__ float kinv[24];

    const int tid = threadIdx.x;  // 192
    const float* ssb = ss + b * 384;

    if (tid < 24) {
        float nk = sqrtf(ssb[192 + h * HD + tid]);
        kinv[tid] = 1.0f / fmaxf(nk, 1e-12f);
    }
    __syncthreads();

    if (tid < 24) {
        const int d = tid;
        float nq = sqrtf(ssb[h * HD + d]);
        float qi = 1.0f / fmaxf(nq, 1e-12f);
        float t = temp[h];
        float row[24];
        float m = -1e30f;
#pragma unroll
        for (int e = 0; e < 24; e++) {
            float v = gram[((long)bh * HD + d) * HD + e] * qi * kinv[e] * t;
            row[e] = v;
            m = fmaxf(m, v);
        }
        float ssum = 0.f;
#pragma unroll
        for (int e = 0; e < 24; e++) { row[e] = expf(row[e] - m); ssum += row[e]; }
        float is = 1.0f / ssum;
#pragma unroll
        for (int e = 0; e < 24; e++) attn[d][e] = row[e] * is;
    }
    __syncthreads();

    // W2[o][h*24+e] = sum_d proj_w[o][h*24+d] * attn[d][e]
    const int o = tid;
    float pw[24];
#pragma unroll
    for (int dd = 0; dd < 24; dd++) pw[dd] = projw[o * CC + h * HD + dd];
#pragma unroll
    for (int e = 0; e < 24; e++) {
        float a = 0.f;
#pragma unroll
        for (int dd = 0; dd < 24; dd++) a += pw[dd] * attn[dd][e];
        w2[((long)b * CC + o) * CC + h * HD + e] = a;
    }
}

// ---------------- launch ----------------
extern "C" void kernel_launch(void* const* d_in, const int* in_sizes, int n_in,
                              void* d_out, int out_size)
{
    const float* x     = (const float*)d_in[0];
    const float* qkvw  = (const float*)d_in[1];
    const float* dww   = (const float*)d_in[2];
    const float* projw = (const float*)d_in[3];
    const float* temp  = (const float*)d_in[4];
    float* out = (float*)d_out;

    float *p_qkv = nullptr, *p_qkvc = nullptr, *p_gram = nullptr, *p_ss = nullptr, *p_w2 = nullptr;
    cudaGetSymbolAddress((void**)&p_qkv,  g_qkv);
    cudaGetSymbolAddress((void**)&p_qkvc, g_qkvc);
    cudaGetSymbolAddress((void**)&p_gram, g_gram);
    cudaGetSymbolAddress((void**)&p_ss,   g_ss);
    cudaGetSymbolAddress((void**)&p_w2,   g_w2);

    // K0: zero accumulators
    zero_kernel<<<72, 256>>>(p_gram, p_ss);

    // K1: qkv = qkv_w @ x   per batch: [576x192]x[192x65536]
    gemm_f32x2<<<dim3(512, 9, 4), 256>>>(
        qkvw, 0L,
        x, (long)CC * NPIX,
        p_qkv, (long)O3 * NPIX);

    // K2: depthwise 3x3 + sumsq for q/k
    dwconv_kernel<<<dim3(BB * O3, 16), 256>>>(p_qkv, dww, p_qkvc, p_ss);

    // K3: Gram matrices
    gram_kernel<<<dim3(8, HEADS, BB), 576>>>(p_qkvc, p_gram);

    // K4: attention softmax + fold projection
    attn_w2_kernel<<<BB * HEADS, 192>>>(p_gram, p_ss, projw, temp, p_w2);

    // K5: out = W2[b] @ v_conv[b]   per batch: [192x192]x[192x65536]
    gemm_f32x2<<<dim3(512, 3, 4), 256>>>(
        p_w2, (long)CC * CC,
        p_qkvc + (long)384 * NPIX, (long)O3 * NPIX,
        out, (long)CC * NPIX);
}

// round 3
// speedup vs baseline: 1.8075x; 1.8075x over previous
#include <cuda_runtime.h>
#include <cuda_bf16.h>
#include <cstdint>

// Problem constants
#define BB 4
#define CC 192
#define O3 576          // 3*CC
#define HEADS 8
#define HD 24
#define IMG 256
#define NPIX 65536      // IMG*IMG

// ---------------- scratch (device globals; no cudaMalloc allowed) ----------------
__device__ float    g_qkv [ (size_t)BB * O3 * NPIX ];     // post 1x1-conv GEMM (fp32)
__device__ float    g_qkvc[ (size_t)BB * 384 * NPIX ];    // post dwconv, q+k only (fp32)
__device__ uint32_t g_b1x [ (size_t)BB * 192 * NPIX ];    // x split: (hi,hi) per k
__device__ uint32_t g_b2x [ (size_t)BB *  96 * NPIX ];    // x split: (lo2k,lo2k+1) per pair
__device__ uint32_t g_b1v [ (size_t)BB * 192 * NPIX ];    // v_conv split: (hi,hi)
__device__ uint32_t g_b2v [ (size_t)BB *  96 * NPIX ];    // v_conv split: lo pairs
__device__ float    g_gram[ BB * HEADS * HD * HD ];
__device__ float    g_ss  [ BB * 384 ];
__device__ float    g_w2  [ BB * CC * CC ];

// ---------------- helpers ----------------
__device__ __forceinline__ uint32_t pkbf(__nv_bfloat16 lo16, __nv_bfloat16 hi16) {
    // element0 (low half) = lo16 arg? NOTE: low half = FIRST k' element.
    return (uint32_t)__bfloat16_as_ushort(hi16) << 16 | (uint32_t)__bfloat16_as_ushort(lo16);
}
__device__ __forceinline__ void splitbf(float v, __nv_bfloat16& h, __nv_bfloat16& l) {
    h = __float2bfloat16(v);
    l = __float2bfloat16(v - __bfloat162float(h));
}
__device__ __forceinline__ void mma16816(float* c, const uint32_t* a, const uint32_t* b) {
    asm volatile(
        "mma.sync.aligned.m16n8k16.row.col.f32.bf16.bf16.f32 "
        "{%0,%1,%2,%3}, {%4,%5,%6,%7}, {%8,%9}, {%0,%1,%2,%3};"
        : "+f"(c[0]), "+f"(c[1]), "+f"(c[2]), "+f"(c[3])
        : "r"(a[0]), "r"(a[1]), "r"(a[2]), "r"(a[3]), "r"(b[0]), "r"(b[1]));
}

// ---------------- K0: zero accumulators ----------------
__global__ void zero_kernel(float* __restrict__ gram, float* __restrict__ ss) {
    int i = blockIdx.x * 256 + threadIdx.x;
    if (i < BB * HEADS * HD * HD) gram[i] = 0.f;
    if (i < BB * 384) ss[i] = 0.f;
}

// ---------------- split_x: build (hi,hi) rows + lo-pair rows from x ----------------
__global__ void __launch_bounds__(256) split_x_kernel(
    const float* __restrict__ x, uint32_t* __restrict__ b1, uint32_t* __restrict__ b2)
{
    const int n = blockIdx.x * 256 + threadIdx.x;
    const int kp = blockIdx.y;          // 0..95
    const int b = blockIdx.z;
    const float* xp = x + ((long)b * 192 + 2 * kp) * NPIX;
    float v0 = xp[n];
    float v1 = xp[NPIX + n];
    __nv_bfloat16 h0, l0, h1, l1;
    splitbf(v0, h0, l0);
    splitbf(v1, h1, l1);
    b1[((long)b * 192 + 2 * kp) * NPIX + n] = pkbf(h0, h0);
    b1[((long)b * 192 + 2 * kp + 1) * NPIX + n] = pkbf(h1, h1);
    b2[((long)b * 96 + kp) * NPIX + n] = pkbf(l0, l1);
}

// ================ split-bf16 tensor-core GEMM =================
// C[m][n] = sum_k W[m][k] * X[k][n], K=192, accuracy via 3-term bf16 split.
// Block tile: 64(M) x 128(N), 8 warps (2m x 4n), warp tile 32x32.
__global__ void __launch_bounds__(256) mma_gemm(
    const float* __restrict__ W, long wBatch,
    const uint32_t* __restrict__ B1, long b1Batch,
    const uint32_t* __restrict__ B2, long b2Batch,
    float* __restrict__ C, long cBatch)
{
    __shared__ uint32_t As1[2][64][17];   // (hi,lo) per original k (16/chunk)
    __shared__ uint32_t As2[2][64][9];    // (hi2k, hi2k+1) per pair (8/chunk)
    __shared__ uint32_t Bs1[2][128][17];  // (hi,hi) per original k
    __shared__ uint32_t Bs2[2][128][9];   // (lo2k, lo2k+1) per pair

    const int tid = threadIdx.x;
    const int wid = tid >> 5, lane = tid & 31;
    const int gid = lane >> 2, tig = lane & 3;
    const int m0 = blockIdx.x * 64;
    const int n0 = blockIdx.y * 128;
    const int bz = blockIdx.z;

    const float* Wb = W + (long)bz * wBatch + (long)m0 * 192;
    const uint32_t* B1b = B1 + (long)bz * b1Batch + n0;
    const uint32_t* B2b = B2 + (long)bz * b2Batch + n0;
    float* Cb = C + (long)bz * cBatch + (long)m0 * NPIX + n0;

    // staging regs
    float aw0, aw1, aw2, aw3;
    uint32_t rb1[8], rb2[4];

    const int am = tid >> 2;            // 0..63
    const int ak = (tid & 3) * 4;       // 0,4,8,12
    const int bn = tid & 127;           // 0..127
    const int bh = tid >> 7;            // 0..1

    float acc[8][4];
#pragma unroll
    for (int i = 0; i < 8; i++)
#pragma unroll
        for (int j = 0; j < 4; j++) acc[i][j] = 0.f;

    const int wm = (wid >> 2) * 32;     // warp m-offset in tile
    const int wn = (wid & 3) * 32;      // warp n-offset in tile

    // ---- load chunk 0
    {
        const float4 av = *(const float4*)(Wb + am * 192 + ak);
        aw0 = av.x; aw1 = av.y; aw2 = av.z; aw3 = av.w;
#pragma unroll
        for (int j = 0; j < 8; j++) rb1[j] = B1b[(long)(bh * 8 + j) * NPIX + bn];
#pragma unroll
        for (int j = 0; j < 4; j++) rb2[j] = B2b[(long)(bh * 4 + j) * NPIX + bn];
    }
    // store chunk 0 -> buf 0
    {
        __nv_bfloat16 h0, l0, h1, l1, h2, l2, h3, l3;
        splitbf(aw0, h0, l0); splitbf(aw1, h1, l1);
        splitbf(aw2, h2, l2); splitbf(aw3, h3, l3);
        As1[0][am][ak + 0] = pkbf(h0, l0);
        As1[0][am][ak + 1] = pkbf(h1, l1);
        As1[0][am][ak + 2] = pkbf(h2, l2);
        As1[0][am][ak + 3] = pkbf(h3, l3);
        As2[0][am][(ak >> 1) + 0] = pkbf(h0, h1);
        As2[0][am][(ak >> 1) + 1] = pkbf(h2, h3);
#pragma unroll
        for (int j = 0; j < 8; j++) Bs1[0][bn][bh * 8 + j] = rb1[j];
#pragma unroll
        for (int j = 0; j < 4; j++) Bs2[0][bn][bh * 4 + j] = rb2[j];
    }
    __syncthreads();

    for (int c = 0; c < 12; c++) {
        const int buf = c & 1;
        // prefetch next chunk into regs
        if (c + 1 < 12) {
            const float4 av = *(const float4*)(Wb + am * 192 + (c + 1) * 16 + ak);
            aw0 = av.x; aw1 = av.y; aw2 = av.z; aw3 = av.w;
#pragma unroll
            for (int j = 0; j < 8; j++)
                rb1[j] = B1b[(long)((c + 1) * 16 + bh * 8 + j) * NPIX + bn];
#pragma unroll
            for (int j = 0; j < 4; j++)
                rb2[j] = B2b[(long)((c + 1) * 8 + bh * 4 + j) * NPIX + bn];
        }

        // ---- compute from smem[buf]: pass1 (2 k-steps) + pass2 (1 k-step)
        {
            const uint32_t* A1 = &As1[buf][0][0];
            const uint32_t* B1s = &Bs1[buf][0][0];
#pragma unroll
            for (int kp0 = 0; kp0 < 16; kp0 += 8) {
                uint32_t a[2][4], b[4][2];
#pragma unroll
                for (int mt = 0; mt < 2; mt++) {
                    const uint32_t* ar = A1 + (wm + mt * 16 + gid) * 17;
                    a[mt][0] = ar[kp0 + tig];
                    a[mt][1] = ar[8 * 17 + kp0 + tig];
                    a[mt][2] = ar[kp0 + 4 + tig];
                    a[mt][3] = ar[8 * 17 + kp0 + 4 + tig];
                }
#pragma unroll
                for (int nt = 0; nt < 4; nt++) {
                    const uint32_t* br = B1s + (wn + nt * 8 + gid) * 17;
                    b[nt][0] = br[kp0 + tig];
                    b[nt][1] = br[kp0 + 4 + tig];
                }
#pragma unroll
                for (int mt = 0; mt < 2; mt++)
#pragma unroll
                    for (int nt = 0; nt < 4; nt++)
                        mma16816(acc[mt * 4 + nt], a[mt], b[nt]);
            }
            const uint32_t* A2 = &As2[buf][0][0];
            const uint32_t* B2s = &Bs2[buf][0][0];
            {
                uint32_t a[2][4], b[4][2];
#pragma unroll
                for (int mt = 0; mt < 2; mt++) {
                    const uint32_t* ar = A2 + (wm + mt * 16 + gid) * 9;
                    a[mt][0] = ar[tig];
                    a[mt][1] = ar[8 * 9 + tig];
                    a[mt][2] = ar[4 + tig];
                    a[mt][3] = ar[8 * 9 + 4 + tig];
                }
#pragma unroll
                for (int nt = 0; nt < 4; nt++) {
                    const uint32_t* br = B2s + (wn + nt * 8 + gid) * 9;
                    b[nt][0] = br[tig];
                    b[nt][1] = br[4 + tig];
                }
#pragma unroll
                for (int mt = 0; mt < 2; mt++)
#pragma unroll
                    for (int nt = 0; nt < 4; nt++)
                        mma16816(acc[mt * 4 + nt], a[mt], b[nt]);
            }
        }

        // ---- convert + store next chunk into other buffer
        if (c + 1 < 12) {
            const int nb = buf ^ 1;
            __nv_bfloat16 h0, l0, h1, l1, h2, l2, h3, l3;
            splitbf(aw0, h0, l0); splitbf(aw1, h1, l1);
            splitbf(aw2, h2, l2); splitbf(aw3, h3, l3);
            As1[nb][am][ak + 0] = pkbf(h0, l0);
            As1[nb][am][ak + 1] = pkbf(h1, l1);
            As1[nb][am][ak + 2] = pkbf(h2, l2);
            As1[nb][am][ak + 3] = pkbf(h3, l3);
            As2[nb][am][(ak >> 1) + 0] = pkbf(h0, h1);
            As2[nb][am][(ak >> 1) + 1] = pkbf(h2, h3);
#pragma unroll
            for (int j = 0; j < 8; j++) Bs1[nb][bn][bh * 8 + j] = rb1[j];
#pragma unroll
            for (int j = 0; j < 4; j++) Bs2[nb][bn][bh * 4 + j] = rb2[j];
        }
        __syncthreads();
    }

    // ---- epilogue
#pragma unroll
    for (int mt = 0; mt < 2; mt++)
#pragma unroll
        for (int nt = 0; nt < 4; nt++) {
            float* base = Cb + (long)(wm + mt * 16 + gid) * NPIX + wn + nt * 8 + tig * 2;
            *(float2*)base = make_float2(acc[mt * 4 + nt][0], acc[mt * 4 + nt][1]);
            *(float2*)(base + (long)8 * NPIX) = make_float2(acc[mt * 4 + nt][2], acc[mt * 4 + nt][3]);
        }
}

// ---------------- dwconv for q,k channels (fp32 out + sumsq) ----------------
__global__ void __launch_bounds__(256) dwconv_qk(
    const float* __restrict__ in, const float* __restrict__ w,
    float* __restrict__ out, float* __restrict__ ss)
{
    const int bidx = blockIdx.x;         // b*384 + ch
    const int b = bidx / 384, ch = bidx % 384;
    const int y0 = blockIdx.y * 16;

    __shared__ float s[18][258];
    __shared__ float red[8];

    const float* ip = in + ((long)b * O3 + ch) * NPIX;
    const int tid = threadIdx.x;

    for (int i = tid; i < 18 * 258; i += 256) {
        int r = i / 258, c = i - r * 258;
        int gy = y0 - 1 + r, gx = c - 1;
        float v = 0.f;
        if (gy >= 0 && gy < IMG && (unsigned)gx < (unsigned)IMG) v = ip[gy * IMG + gx];
        s[r][c] = v;
    }
    const float* wp = w + ch * 9;
    float w00 = wp[0], w01 = wp[1], w02 = wp[2];
    float w10 = wp[3], w11 = wp[4], w12 = wp[5];
    float w20 = wp[6], w21 = wp[7], w22 = wp[8];
    __syncthreads();

    float* op = out + ((long)b * 384 + ch) * NPIX + (long)y0 * IMG;
    const int x = tid;
    float sq = 0.f;
#pragma unroll
    for (int yy = 0; yy < 16; yy++) {
        float v = s[yy    ][x] * w00 + s[yy    ][x + 1] * w01 + s[yy    ][x + 2] * w02
                + s[yy + 1][x] * w10 + s[yy + 1][x + 1] * w11 + s[yy + 1][x + 2] * w12
                + s[yy + 2][x] * w20 + s[yy + 2][x + 1] * w21 + s[yy + 2][x + 2] * w22;
        op[yy * IMG + x] = v;
        sq += v * v;
    }
#pragma unroll
    for (int o = 16; o > 0; o >>= 1) sq += __shfl_xor_sync(0xffffffffu, sq, o);
    if ((tid & 31) == 0) red[tid >> 5] = sq;
    __syncthreads();
    if (tid == 0) {
        float t = 0.f;
#pragma unroll
        for (int i = 0; i < 8; i++) t += red[i];
        atomicAdd(&ss[b * 384 + ch], t);
    }
}

// ---------------- dwconv for v channel-pairs -> split-bf16 outputs ----------------
__global__ void __launch_bounds__(256) dwconv_v(
    const float* __restrict__ in, const float* __restrict__ w,
    uint32_t* __restrict__ b1v, uint32_t* __restrict__ b2v)
{
    const int bidx = blockIdx.x;         // b*96 + cp
    const int b = bidx / 96, cp = bidx % 96;
    const int ch0 = 384 + cp * 2;        // within qkv
    const int y0 = blockIdx.y * 16;

    __shared__ float s[2][18][258];

    const float* ip = in + ((long)b * O3 + ch0) * NPIX;
    const int tid = threadIdx.x;

    for (int i = tid; i < 2 * 18 * 258; i += 256) {
        int pl = i / (18 * 258);
        int rem = i - pl * (18 * 258);
        int r = rem / 258, c = rem - r * 258;
        int gy = y0 - 1 + r, gx = c - 1;
        float v = 0.f;
        if (gy >= 0 && gy < IMG && (unsigned)gx < (unsigned)IMG)
            v = ip[(long)pl * NPIX + gy * IMG + gx];
        s[pl][r][c] = v;
    }
    const float* wp0 = w + ch0 * 9;
    float a00 = wp0[0], a01 = wp0[1], a02 = wp0[2];
    float a10 = wp0[3], a11 = wp0[4], a12 = wp0[5];
    float a20 = wp0[6], a21 = wp0[7], a22 = wp0[8];
    const float* wp1 = wp0 + 9;
    float c00 = wp1[0], c01 = wp1[1], c02 = wp1[2];
    float c10 = wp1[3], c11 = wp1[4], c12 = wp1[5];
    float c20 = wp1[6], c21 = wp1[7], c22 = wp1[8];
    __syncthreads();

    uint32_t* o1a = b1v + ((long)b * 192 + cp * 2) * NPIX + (long)y0 * IMG;
    uint32_t* o1b = o1a + (long)NPIX;
    uint32_t* o2 = b2v + ((long)b * 96 + cp) * NPIX + (long)y0 * IMG;
    const int x = tid;
#pragma unroll
    for (int yy = 0; yy < 16; yy++) {
        float v0 = s[0][yy    ][x] * a00 + s[0][yy    ][x + 1] * a01 + s[0][yy    ][x + 2] * a02
                 + s[0][yy + 1][x] * a10 + s[0][yy + 1][x + 1] * a11 + s[0][yy + 1][x + 2] * a12
                 + s[0][yy + 2][x] * a20 + s[0][yy + 2][x + 1] * a21 + s[0][yy + 2][x + 2] * a22;
        float v1 = s[1][yy    ][x] * c00 + s[1][yy    ][x + 1] * c01 + s[1][yy    ][x + 2] * c02
                 + s[1][yy + 1][x] * c10 + s[1][yy + 1][x + 1] * c11 + s[1][yy + 1][x + 2] * c12
                 + s[1][yy + 2][x] * c20 + s[1][yy + 2][x + 1] * c21 + s[1][yy + 2][x + 2] * c22;
        __nv_bfloat16 h0, l0, h1, l1;
        splitbf(v0, h0, l0);
        splitbf(v1, h1, l1);
        o1a[yy * IMG + x] = pkbf(h0, h0);
        o1b[yy * IMG + x] = pkbf(h1, h1);
        o2[yy * IMG + x] = pkbf(l0, l1);
    }
}

// ---------------- K3: Gram matrices, 3x3 register blocking ----------------
__global__ void __launch_bounds__(256) gram_kernel(
    const float* __restrict__ qkvc, float* __restrict__ gram)
{
    const int bh = blockIdx.y;
    const int b = bh >> 3, h = bh & 7;
    const long nbase = (long)blockIdx.x * 4096;

    __shared__ float sq[24][132];
    __shared__ float sk[24][132];

    const float* qp = qkvc + ((long)b * 384 + h * HD) * NPIX;
    const float* kp = qp + (long)CC * NPIX;

    const int tid = threadIdx.x;
    const int g = tid >> 6;
    const int id = tid & 63;
    const int d0 = (id >> 3) * 3;
    const int e0 = (id & 7) * 3;

    float a00 = 0.f, a01 = 0.f, a02 = 0.f;
    float a10 = 0.f, a11 = 0.f, a12 = 0.f;
    float a20 = 0.f, a21 = 0.f, a22 = 0.f;

    for (int it = 0; it < 32; it++) {
        const long n0 = nbase + it * 128;
        for (int i = tid; i < 24 * 128; i += 256) {
            int r = i >> 7, c = i & 127;
            sq[r][c] = qp[(long)r * NPIX + n0 + c];
            sk[r][c] = kp[(long)r * NPIX + n0 + c];
        }
        __syncthreads();
        const int p0 = g * 32;
#pragma unroll 8
        for (int pp = 0; pp < 32; pp++) {
            const int p = p0 + pp;
            float q0 = sq[d0][p], q1 = sq[d0 + 1][p], q2 = sq[d0 + 2][p];
            float k0 = sk[e0][p], k1 = sk[e0 + 1][p], k2 = sk[e0 + 2][p];
            a00 += q0 * k0; a01 += q0 * k1; a02 += q0 * k2;
            a10 += q1 * k0; a11 += q1 * k1; a12 += q1 * k2;
            a20 += q2 * k0; a21 += q2 * k1; a22 += q2 * k2;
        }
        __syncthreads();
    }
    float* gp = gram + ((long)bh * HD) * HD;
    atomicAdd(&gp[(d0    ) * HD + e0    ], a00);
    atomicAdd(&gp[(d0    ) * HD + e0 + 1], a01);
    atomicAdd(&gp[(d0    ) * HD + e0 + 2], a02);
    atomicAdd(&gp[(d0 + 1) * HD + e0    ], a10);
    atomicAdd(&gp[(d0 + 1) * HD + e0 + 1], a11);
    atomicAdd(&gp[(d0 + 1) * HD + e0 + 2], a12);
    atomicAdd(&gp[(d0 + 2) * HD + e0    ], a20);
    atomicAdd(&gp[(d0 + 2) * HD + e0 + 1], a21);
    atomicAdd(&gp[(d0 + 2) * HD + e0 + 2], a22);
}

// ---------------- K4: normalize + softmax + fold projection into W2 ----------------
__global__ void __launch_bounds__(192) attn_w2_kernel(
    const float* __restrict__ gram, const float* __restrict__ ss,
    const float* __restrict__ projw, const float* __restrict__ temp,
    float* __restrict__ w2)
{
    const int bh = blockIdx.x;
    const int b = bh >> 3, h = bh & 7;
    __shared__ float attn[24][24];
    __shared__ float kinv[24];

    const int tid = threadIdx.x;
    const float* ssb = ss + b * 384;

    if (tid < 24) {
        float nk = sqrtf(ssb[192 + h * HD + tid]);
        kinv[tid] = 1.0f / fmaxf(nk, 1e-12f);
    }
    __syncthreads();

    if (tid < 24) {
        const int d = tid;
        float nq = sqrtf(ssb[h * HD + d]);
        float qi = 1.0f / fmaxf(nq, 1e-12f);
        float t = temp[h];
        float row[24];
        float m = -1e30f;
#pragma unroll
        for (int e = 0; e < 24; e++) {
            float v = gram[((long)bh * HD + d) * HD + e] * qi * kinv[e] * t;
            row[e] = v;
            m = fmaxf(m, v);
        }
        float ssum = 0.f;
#pragma unroll
        for (int e = 0; e < 24; e++) { row[e] = expf(row[e] - m); ssum += row[e]; }
        float is = 1.0f / ssum;
#pragma unroll
        for (int e = 0; e < 24; e++) attn[d][e] = row[e] * is;
    }
    __syncthreads();

    const int o = tid;
    float pw[24];
#pragma unroll
    for (int dd = 0; dd < 24; dd++) pw[dd] = projw[o * CC + h * HD + dd];
#pragma unroll
    for (int e = 0; e < 24; e++) {
        float a = 0.f;
#pragma unroll
        for (int dd = 0; dd < 24; dd++) a += pw[dd] * attn[dd][e];
        w2[((long)b * CC + o) * CC + h * HD + e] = a;
    }
}

// ---------------- launch ----------------
extern "C" void kernel_launch(void* const* d_in, const int* in_sizes, int n_in,
                              void* d_out, int out_size)
{
    const float* x     = (const float*)d_in[0];
    const float* qkvw  = (const float*)d_in[1];
    const float* dww   = (const float*)d_in[2];
    const float* projw = (const float*)d_in[3];
    const float* temp  = (const float*)d_in[4];
    float* out = (float*)d_out;

    float *p_qkv, *p_qkvc, *p_gram, *p_ss, *p_w2;
    uint32_t *p_b1x, *p_b2x, *p_b1v, *p_b2v;
    cudaGetSymbolAddress((void**)&p_qkv,  g_qkv);
    cudaGetSymbolAddress((void**)&p_qkvc, g_qkvc);
    cudaGetSymbolAddress((void**)&p_gram, g_gram);
    cudaGetSymbolAddress((void**)&p_ss,   g_ss);
    cudaGetSymbolAddress((void**)&p_w2,   g_w2);
    cudaGetSymbolAddress((void**)&p_b1x,  g_b1x);
    cudaGetSymbolAddress((void**)&p_b2x,  g_b2x);
    cudaGetSymbolAddress((void**)&p_b1v,  g_b1v);
    cudaGetSymbolAddress((void**)&p_b2v,  g_b2v);

    // K0: zero accumulators
    zero_kernel<<<72, 256>>>(p_gram, p_ss);

    // split x into bf16 hi/lo operand buffers
    split_x_kernel<<<dim3(NPIX / 256, 96, BB), 256>>>(x, p_b1x, p_b2x);

    // K1: qkv = qkv_w @ x  (per batch [576x192]x[192x65536]) — grid m-fastest for B L2 reuse
    mma_gemm<<<dim3(9, 512, BB), 256>>>(
        qkvw, 0L,
        p_b1x, (long)192 * NPIX,
        p_b2x, (long)96 * NPIX,
        p_qkv, (long)O3 * NPIX);

    // K2a: depthwise 3x3 for q,k (fp32 + sumsq)
    dwconv_qk<<<dim3(BB * 384, 16), 256>>>(p_qkv, dww, p_qkvc, p_ss);

    // K2b: depthwise 3x3 for v channel-pairs -> split bf16 operands
    dwconv_v<<<dim3(BB * 96, 16), 256>>>(p_qkv, dww, p_b1v, p_b2v);

    // K3: Gram matrices
    gram_kernel<<<dim3(16, BB * HEADS), 256>>>(p_qkvc, p_gram);

    // K4: attention softmax + fold projection
    attn_w2_kernel<<<BB * HEADS, 192>>>(p_gram, p_ss, projw, temp, p_w2);

    // K5: out = W2[b] @ v_conv[b]  (per batch [192x192]x[192x65536])
    mma_gemm<<<dim3(3, 512, BB), 256>>>(
        p_w2, (long)CC * CC,
        p_b1v, (long)192 * NPIX,
        p_b2v, (long)96 * NPIX,
        out, (long)CC * NPIX);
}